// round 16
// baseline (speedup 1.0000x reference)
#include <cuda_runtime.h>
#include <cuda_fp16.h>

#define N_NODES 100000
#define N_EDGES 3200000
#define FEAT 16
#define SCAN_TILE 1024
#define MAX_TILES 128

// Scratch in __device__ globals (no allocations allowed).
// Invariant: g_degi and g_tile are zero at kernel_launch entry (BSS-zero on
// first call; k_agg2's tail re-zeroes them every call).
__device__ int   g_degi     [N_NODES];
__device__ int   g_rowstart [N_NODES + 1];
__device__ unsigned long long g_tile[MAX_TILES];   // lookback state
__device__ unsigned short g_rank[N_EDGES];         // edge rank within dst bucket
__device__ int   g_esrc     [N_EDGES];             // src ids, dst-sorted
__device__ float g_dinv     [N_NODES];
__device__ uint2 g_hsh1     [N_NODES * 4];         // fp16x2 messages, 32B/node
__device__ uint2 g_hsh2     [N_NODES * 4];

// ------------------------------------------------------------------ hist ----
// Histogram AND per-edge rank (the atomic's return value) in one pass.
__global__ void k_hist(const int* __restrict__ dst, int E) {
    int e = blockIdx.x * blockDim.x + threadIdx.x;
    if (e >= E) return;
    int d = __ldg(dst + e);
    int r = atomicAdd(&g_degi[d], 1);
    g_rank[e] = (unsigned short)r;
}

// ------------------- single-pass scan (lookback) + layer-1 transform --------
// status in bits[33:32]: 1 = aggregate published, 2 = inclusive prefix.
// After the scan epilogue, the same threads run transform1 for their node:
// the extra work sits entirely AFTER this tile's aggregate publish, so it
// does not lengthen the cross-tile lookback chain.
__global__ void __launch_bounds__(SCAN_TILE)
k_scan_t1(const float* __restrict__ x, const float* __restrict__ W,
          int n, int E) {
    __shared__ int wsum[32];
    __shared__ int s_prefix;
    __shared__ float sW[16][16];
    int t = threadIdx.x, bid = blockIdx.x;
    if (t < 256) sW[t >> 4][t & 15] = W[t];

    int idx = bid * SCAN_TILE + t;
    int v = (idx < n) ? g_degi[idx] : 0;
    int lane = t & 31, wid = t >> 5;

    int s = v;
#pragma unroll
    for (int off = 1; off < 32; off <<= 1) {
        int u = __shfl_up_sync(0xffffffffu, s, off);
        if (lane >= off) s += u;
    }
    if (lane == 31) wsum[wid] = s;
    __syncthreads();
    if (wid == 0) {
        int ws = wsum[lane];
#pragma unroll
        for (int off = 1; off < 32; off <<= 1) {
            int u = __shfl_up_sync(0xffffffffu, ws, off);
            if (lane >= off) ws += u;
        }
        wsum[lane] = ws;
    }
    __syncthreads();
    int incl  = s + ((wid > 0) ? wsum[wid - 1] : 0);
    int total = wsum[31];

    // publish + lookback (warp 0)
    if (wid == 0) {
        if (bid == 0) {
            if (lane == 0) {
                s_prefix = 0;
                atomicExch(&g_tile[0], (2ULL << 32) | (unsigned)total);
            }
        } else {
            if (lane == 0)
                atomicExch(&g_tile[bid], (1ULL << 32) | (unsigned)total);
            int ex = 0, base = bid - 1;
            bool done = false;
            while (!done) {
                int i = base - lane;
                unsigned long long stw = (i >= 0) ? atomicAdd(&g_tile[i], 0ULL)
                                                  : (1ULL << 32);   // AGG,0
                unsigned stat = (unsigned)(stw >> 32);
                int val = (int)(unsigned)stw;
                unsigned pre_mask  = __ballot_sync(0xffffffffu, stat == 2u);
                unsigned none_mask = __ballot_sync(0xffffffffu, stat == 0u);
                if (pre_mask) {
                    int lp = __ffs(pre_mask) - 1;          // closest PREFIX
                    if ((none_mask & ((1u << lp) - 1)) == 0) {
                        int c = (lane <= lp) ? val : 0;
#pragma unroll
                        for (int off = 16; off; off >>= 1)
                            c += __shfl_down_sync(0xffffffffu, c, off);
                        ex += __shfl_sync(0xffffffffu, c, 0);
                        done = true;
                    }
                } else if (none_mask == 0) {               // window all AGG
                    int c = val;
#pragma unroll
                    for (int off = 16; off; off >>= 1)
                        c += __shfl_down_sync(0xffffffffu, c, off);
                    ex += __shfl_sync(0xffffffffu, c, 0);
                    base -= 32;                            // block0 is PRE, so
                }                                          // base never < 0 here
            }
            if (lane == 0) {
                s_prefix = ex;
                atomicExch(&g_tile[bid], (2ULL << 32) | (unsigned)(ex + total));
            }
        }
    }
    __syncthreads();
    if (idx < n)
        g_rowstart[idx] = s_prefix + incl - v;   // global exclusive
    if (idx == 0) g_rowstart[n] = E;

    // ---- fused layer-1 transform (uses v = degree, sW = W1) ----
    if (idx >= n) return;
    float di = rsqrtf((float)v + 1.0f);          // +1 self loop
    g_dinv[idx] = di;

    const float4* xr = (const float4*)(x + (size_t)idx * FEAT);
    float xin[16];
#pragma unroll
    for (int q = 0; q < 4; q++) {
        float4 xv = xr[q];
        xin[4*q+0] = xv.x; xin[4*q+1] = xv.y;
        xin[4*q+2] = xv.z; xin[4*q+3] = xv.w;
    }
    uint2* hp = &g_hsh1[(size_t)idx * 4];
#pragma unroll
    for (int qq = 0; qq < 4; qq++) {
        float o[4];
#pragma unroll
        for (int jj = 0; jj < 4; jj++) {
            int j = 4*qq + jj;
            float acc = 0.0f;
#pragma unroll
            for (int k = 0; k < 16; k++) acc = fmaf(xin[k], sW[k][j], acc);
            o[jj] = acc * di;
        }
        __half2 p0 = __floats2half2_rn(o[0], o[1]);
        __half2 p1 = __floats2half2_rn(o[2], o[3]);
        hp[qq] = make_uint2(*(unsigned*)&p0, *(unsigned*)&p1);
    }
}

// ----------------------------------------------------------------- bucket ---
// Atomic-free placement: pos = rowstart[dst] + rank (saved during hist).
__global__ void k_bucket(const int* __restrict__ src,
                         const int* __restrict__ dst, int E) {
    int e = blockIdx.x * blockDim.x + threadIdx.x;
    if (e >= E) return;
    int d = __ldg(dst + e);
    int pos = __ldg(&g_rowstart[d]) + (int)g_rank[e];
    g_esrc[pos] = __ldg(src + e);
}

// --------------------------------- agg1 + transform2 (block-smem fusion) ----
// 8 warps = 8 nodes per block. Each warp gathers+reduces its node's layer-1
// messages (lanes = 8 edge-slots x 4 quarters), applies relu(*di+b1), and
// parks hin in smem. Then 64 dense threads do the 8-node 16x16 matvec from
// smem and store the fp16 layer-2 messages. No shfl matvec, no fp32 agg
// round-trip through global.
__global__ void k_agg1t2(const float* __restrict__ W2,
                         const float* __restrict__ b1, int n) {
    __shared__ float sW[16][16];
    __shared__ float sb[16];
    __shared__ float sh_hin[8][16];
    __shared__ float sh_di[8];
    int t = threadIdx.x;
    if (t < 256) sW[t >> 4][t & 15] = W2[t];
    if (t < 16) sb[t] = b1[t];

    int wid  = t >> 5;
    int lane = t & 31;
    int gw   = blockIdx.x * 8 + wid;
    int q    = lane & 3;
    int slot = lane >> 2;
    bool active = (gw < n);

    float4 acc = make_float4(0.f, 0.f, 0.f, 0.f);
    if (active) {
        int beg = g_rowstart[gw];
        int end = g_rowstart[gw + 1];
#pragma unroll 2
        for (int j = beg + slot; j < end; j += 8) {
            int s = __ldg(&g_esrc[j]);
            uint2 w = __ldg(&g_hsh1[(size_t)s * 4 + q]);
            float2 f0 = __half22float2(*(__half2*)&w.x);
            float2 f1 = __half22float2(*(__half2*)&w.y);
            acc.x += f0.x; acc.y += f0.y; acc.z += f1.x; acc.w += f1.y;
        }
    }
#pragma unroll
    for (int off = 16; off >= 4; off >>= 1) {
        acc.x += __shfl_down_sync(0xffffffffu, acc.x, off);
        acc.y += __shfl_down_sync(0xffffffffu, acc.y, off);
        acc.z += __shfl_down_sync(0xffffffffu, acc.z, off);
        acc.w += __shfl_down_sync(0xffffffffu, acc.w, off);
    }
    if (active && lane < 4) {
        uint2 sw = __ldg(&g_hsh1[(size_t)gw * 4 + lane]);   // self loop
        float2 s0 = __half22float2(*(__half2*)&sw.x);
        float2 s1 = __half22float2(*(__half2*)&sw.y);
        float di = g_dinv[gw];
        if (lane == 0) sh_di[wid] = di;
        sh_hin[wid][lane*4+0] = fmaxf(fmaf(acc.x + s0.x, di, sb[lane*4+0]), 0.0f);
        sh_hin[wid][lane*4+1] = fmaxf(fmaf(acc.y + s0.y, di, sb[lane*4+1]), 0.0f);
        sh_hin[wid][lane*4+2] = fmaxf(fmaf(acc.z + s1.x, di, sb[lane*4+2]), 0.0f);
        sh_hin[wid][lane*4+3] = fmaxf(fmaf(acc.w + s1.y, di, sb[lane*4+3]), 0.0f);
    }
    __syncthreads();

    // 64 threads: 8 nodes x 8 half2-pairs; each computes 2 output features.
    if (t < 64) {
        int w = t >> 3, p = t & 7;
        int node = blockIdx.x * 8 + w;
        if (node < n) {
            float di = sh_di[w];
            float o0 = 0.0f, o1 = 0.0f;
#pragma unroll
            for (int k = 0; k < 16; k++) {
                float hk = sh_hin[w][k];
                o0 = fmaf(hk, sW[k][2*p+0], o0);
                o1 = fmaf(hk, sW[k][2*p+1], o1);
            }
            __half2 h = __floats2half2_rn(o0 * di, o1 * di);
            ((unsigned*)g_hsh2)[(size_t)node * 8 + p] = *(unsigned*)&h;
        }
    }
}

// ------------------------- agg2 + output epilogue + next-call zeroing -------
__global__ void k_agg2(const float* __restrict__ b2,
                       float* __restrict__ out, int n) {
    int gw   = (blockIdx.x * blockDim.x + threadIdx.x) >> 5;
    int lane = threadIdx.x & 31;

    // restore the zero-invariant for the next kernel_launch call
    if (blockIdx.x == 0 && threadIdx.x < MAX_TILES)
        g_tile[threadIdx.x] = 0ULL;
    if (gw < n && lane == 0) g_degi[gw] = 0;

    if (gw >= n) return;
    int q    = lane & 3;
    int slot = lane >> 2;

    int beg = g_rowstart[gw];
    int end = g_rowstart[gw + 1];

    float4 acc = make_float4(0.f, 0.f, 0.f, 0.f);
#pragma unroll 2
    for (int j = beg + slot; j < end; j += 8) {
        int s = __ldg(&g_esrc[j]);
        uint2 w = __ldg(&g_hsh2[(size_t)s * 4 + q]);
        float2 f0 = __half22float2(*(__half2*)&w.x);
        float2 f1 = __half22float2(*(__half2*)&w.y);
        acc.x += f0.x; acc.y += f0.y; acc.z += f1.x; acc.w += f1.y;
    }
#pragma unroll
    for (int off = 16; off >= 4; off >>= 1) {
        acc.x += __shfl_down_sync(0xffffffffu, acc.x, off);
        acc.y += __shfl_down_sync(0xffffffffu, acc.y, off);
        acc.z += __shfl_down_sync(0xffffffffu, acc.z, off);
        acc.w += __shfl_down_sync(0xffffffffu, acc.w, off);
    }
    if (lane < 4) {
        uint2 sw = __ldg(&g_hsh2[(size_t)gw * 4 + lane]);   // self loop
        float2 s0 = __half22float2(*(__half2*)&sw.x);
        float2 s1 = __half22float2(*(__half2*)&sw.y);
        float di = g_dinv[gw];
        float4 bb = __ldg(((const float4*)b2) + lane);
        float4 o;
        o.x = fmaf(acc.x + s0.x, di, bb.x);
        o.y = fmaf(acc.y + s0.y, di, bb.y);
        o.z = fmaf(acc.z + s1.x, di, bb.z);
        o.w = fmaf(acc.w + s1.y, di, bb.w);
        ((float4*)out)[(size_t)gw * 4 + lane] = o;
    }
}

// ---------------------------------------------------------------- launch ----
extern "C" void kernel_launch(void* const* d_in, const int* in_sizes, int n_in,
                              void* d_out, int out_size) {
    const float* x    = (const float*)d_in[0];
    const int*   eidx = (const int*)  d_in[1];
    const float* W1   = (const float*)d_in[2];
    const float* b1   = (const float*)d_in[3];
    const float* W2   = (const float*)d_in[4];
    const float* b2   = (const float*)d_in[5];
    float* out = (float*)d_out;

    int n = in_sizes[0] / FEAT;       // 100000
    int E = in_sizes[1] / 2;          // 3200000
    const int* src = eidx;
    const int* dst = eidx + E;

    const int B = 256;
    int ge = (E + B - 1) / B;                    // edge-parallel grid
    int nt = (n + SCAN_TILE - 1) / SCAN_TILE;    // scan tiles (98)
    int gw = (n * 32 + B - 1) / B;               // warp-per-node grid
    int g8 = (n + 7) / 8;                        // 8-nodes-per-block grid

    k_hist   <<<ge, B>>>(dst, E);                // degree + rank
    k_scan_t1<<<nt, SCAN_TILE>>>(x, W1, n, E);   // rowstart + layer-1 xform
    k_bucket <<<ge, B>>>(src, dst, E);           // dst-sorted src list
    k_agg1t2 <<<g8, B>>>(W2, b1, n);             // agg1 + layer-2 xform
    k_agg2   <<<gw, B>>>(b2, out, n);            // agg2 + epilogue + re-zero
}